// round 17
// baseline (speedup 1.0000x reference)
#include <cuda_runtime.h>
#include <cuda_bf16.h>
#include <cuda_fp16.h>
#include <cstdint>

// Problem constants
#define NN   50000
#define EE   800000
#define INC  128
#define HIDC 256
#define OUTC 128
#define MAXD 64     // padded CSR slots per node; P(deg>64) ~ 1e-19 for Poisson(16)

// ---------------- device scratch (static globals; no allocation) ----------------
__device__ int   g_deg[NN];
__device__ int   g_colpad[(size_t)NN * MAXD];   // 12.8 MB padded CSR
__device__ int   g_is64;

// bf16 limb planes (hi/lo) for GEMM operands (16B aligned for cp.async)
__device__ __align__(16) unsigned short g_xh [(size_t)NN * INC],  g_xl [(size_t)NN * INC];
__device__ __align__(16) unsigned short g_m1h[(size_t)NN * INC],  g_m1l[(size_t)NN * INC];
__device__ __align__(16) unsigned short g_hh [(size_t)NN * HIDC], g_hl [(size_t)NN * HIDC];
// fp16 gather operands for aggregation
__device__ __align__(16) unsigned short g_xf16[(size_t)NN * INC];
__device__ __align__(16) unsigned short g_pf16[(size_t)NN * OUTC];  // p = h @ W2l^T (fp16)
__device__ float g_q[(size_t)NN * OUTC];   // q = h @ W2r^T + b2 (fp32)

// weight limb planes
__device__ __align__(16) unsigned short g_w1lh[HIDC * INC],  g_w1ll[HIDC * INC];
__device__ __align__(16) unsigned short g_w1rh[HIDC * INC],  g_w1rl[HIDC * INC];
__device__ __align__(16) unsigned short g_w2lh[OUTC * HIDC], g_w2ll[OUTC * HIDC];
__device__ __align__(16) unsigned short g_w2rh[OUTC * HIDC], g_w2rl[OUTC * HIDC];

__device__ __forceinline__ void split1(float v, unsigned short& h, unsigned short& l) {
    __nv_bfloat16 hb = __float2bfloat16_rn(v);
    float lo = v - __bfloat162float(hb);
    __nv_bfloat16 lb = __float2bfloat16_rn(lo);
    h = *(unsigned short*)&hb;
    l = *(unsigned short*)&lb;
}

__device__ __forceinline__ int load_edge(const void* ei_raw, long long idx, int is64) {
    if (is64) return (int)((const long long*)ei_raw)[idx];
    return ((const int*)ei_raw)[idx];
}

// ---------------- fused prep: weight splits | x split(+fp16) | deg zero + dtype --
#define SWBLK 512     // 4*HIDC*INC/256
#define SXBLK 6250    // NN*INC/4/256
__global__ void prep_kernel(const void* __restrict__ ei_raw, const float* __restrict__ x,
                            const float* __restrict__ W1l, const float* __restrict__ W1r,
                            const float* __restrict__ W2l, const float* __restrict__ W2r) {
    int b = blockIdx.x, t = threadIdx.x;
    if (b < SWBLK) {
        const int S = HIDC * INC;
        int i = b * 256 + t;
        if (i < S)            split1(W1l[i], g_w1lh[i], g_w1ll[i]);
        else if (i < 2 * S) { int j = i - S;     split1(W1r[j], g_w1rh[j], g_w1rl[j]); }
        else if (i < 3 * S) { int j = i - 2 * S; split1(W2l[j], g_w2lh[j], g_w2ll[j]); }
        else                { int j = i - 3 * S; split1(W2r[j], g_w2rh[j], g_w2rl[j]); }
    } else if (b < SWBLK + SXBLK) {
        int i = (b - SWBLK) * 256 + t;          // float4 index
        if (i < NN * INC / 4) {
            float4 v = ((const float4*)x)[i];
            ushort4 hv, lv;
            split1(v.x, hv.x, lv.x); split1(v.y, hv.y, lv.y);
            split1(v.z, hv.z, lv.z); split1(v.w, hv.w, lv.w);
            ((ushort4*)g_xh)[i] = hv;
            ((ushort4*)g_xl)[i] = lv;
            __half2 f01 = __floats2half2_rn(v.x, v.y);
            __half2 f23 = __floats2half2_rn(v.z, v.w);
            uint2 fv;
            fv.x = *(unsigned*)&f01; fv.y = *(unsigned*)&f23;
            ((uint2*)g_xf16)[i] = fv;
        }
    } else {
        int bb = b - SWBLK - SXBLK;
        int i = bb * 256 + t;
        if (i < NN) g_deg[i] = 0;
        if (bb == 0 && t < 32) {
            const unsigned* w = (const unsigned*)ei_raw;
            unsigned acc = 0;
            for (int i2 = t; i2 < 128; i2 += 32) acc |= w[2 * i2 + 1];
            #pragma unroll
            for (int off = 16; off; off >>= 1) acc |= __shfl_xor_sync(0xFFFFFFFFu, acc, off);
            if (t == 0) g_is64 = (acc == 0) ? 1 : 0;
        }
    }
}

// ---------------- single-kernel padded-CSR build --------------------------------
__global__ void fillpad_kernel(const void* __restrict__ ei_raw) {
    int is64 = g_is64;
    int i = blockIdx.x * blockDim.x + threadIdx.x;
    if (i >= EE) return;
    int src = load_edge(ei_raw, (long long)i, is64);
    int dst = load_edge(ei_raw, (long long)EE + i, is64);
    int p = atomicAdd(&g_deg[dst], 1);
    if (p < MAXD) g_colpad[(size_t)dst * MAXD + p] = src;
}

// ---------------- mean aggregation over 128-channel fp16 features --------------
// MODE 0: m1 = mean_agg(g_xf16) -> bf16 limb planes
// MODE 1: out = mean_agg(g_pf16) + g_q  (fp32, final output)
template <int MODE>
__global__ void agg128_kernel(float* __restrict__ outp) {
    const unsigned short* __restrict__ in = (MODE == 0) ? g_xf16 : g_pf16;

    int warp = (blockIdx.x * blockDim.x + threadIdx.x) >> 5;
    if (warp >= NN) return;
    int lane = threadIdx.x & 31;

    int d = min(__ldg(&g_deg[warp]), MAXD);
    const int* cols = g_colpad + (size_t)warp * MAXD;
    float inv = 1.0f / (float)max(d, 1);

    float4 acc0 = make_float4(0.f, 0.f, 0.f, 0.f);
    float4 acc1 = make_float4(0.f, 0.f, 0.f, 0.f);
    float4 acc2 = make_float4(0.f, 0.f, 0.f, 0.f);
    float4 acc3 = make_float4(0.f, 0.f, 0.f, 0.f);

    auto accum = [&](float4& a, uint2 v) {
        float2 f0 = __half22float2(*(__half2*)&v.x);
        float2 f1 = __half22float2(*(__half2*)&v.y);
        a.x += f0.x; a.y += f0.y; a.z += f1.x; a.w += f1.y;
    };

    int j = 0;
    for (; j + 3 < d; j += 4) {
        int s0 = __ldg(cols + j),     s1 = __ldg(cols + j + 1);
        int s2 = __ldg(cols + j + 2), s3 = __ldg(cols + j + 3);
        uint2 v0 = __ldg((const uint2*)(in + (size_t)s0 * 128) + lane);
        uint2 v1 = __ldg((const uint2*)(in + (size_t)s1 * 128) + lane);
        uint2 v2 = __ldg((const uint2*)(in + (size_t)s2 * 128) + lane);
        uint2 v3 = __ldg((const uint2*)(in + (size_t)s3 * 128) + lane);
        accum(acc0, v0); accum(acc1, v1); accum(acc2, v2); accum(acc3, v3);
    }
    for (; j < d; j++) {
        int s = __ldg(cols + j);
        uint2 v = __ldg((const uint2*)(in + (size_t)s * 128) + lane);
        accum(acc0, v);
    }

    float4 r;
    r.x = (acc0.x + acc1.x + acc2.x + acc3.x) * inv;
    r.y = (acc0.y + acc1.y + acc2.y + acc3.y) * inv;
    r.z = (acc0.z + acc1.z + acc2.z + acc3.z) * inv;
    r.w = (acc0.w + acc1.w + acc2.w + acc3.w) * inv;

    if (MODE == 0) {
        ushort4 hv, lv;
        split1(r.x, hv.x, lv.x); split1(r.y, hv.y, lv.y);
        split1(r.z, hv.z, lv.z); split1(r.w, hv.w, lv.w);
        ((ushort4*)g_m1h)[(size_t)warp * 32 + lane] = hv;
        ((ushort4*)g_m1l)[(size_t)warp * 32 + lane] = lv;
    } else {
        float4 qv = __ldg((const float4*)((const float*)g_q + (size_t)warp * 128) + lane);
        r.x += qv.x; r.y += qv.y; r.z += qv.z; r.w += qv.w;
        ((float4*)(outp + (size_t)warp * 128))[lane] = r;
    }
}

// ---------------- bf16 2-limb tensor-core GEMM (ldmatrix + cp.async pipeline) --
__device__ __forceinline__ void mma_bf16(float c[4], const unsigned a[4], const unsigned b[2]) {
    asm volatile(
        "mma.sync.aligned.m16n8k16.row.col.f32.bf16.bf16.f32 "
        "{%0,%1,%2,%3},{%4,%5,%6,%7},{%8,%9},{%0,%1,%2,%3};"
        : "+f"(c[0]), "+f"(c[1]), "+f"(c[2]), "+f"(c[3])
        : "r"(a[0]), "r"(a[1]), "r"(a[2]), "r"(a[3]), "r"(b[0]), "r"(b[1]));
}

__device__ __forceinline__ void ldsm_x4(unsigned r[4], unsigned addr) {
    asm volatile("ldmatrix.sync.aligned.m8n8.x4.shared.b16 {%0,%1,%2,%3}, [%4];"
        : "=r"(r[0]), "=r"(r[1]), "=r"(r[2]), "=r"(r[3]) : "r"(addr));
}

__device__ __forceinline__ void cpa16(unsigned smem, const void* g) {
    asm volatile("cp.async.cg.shared.global [%0], [%1], 16;" :: "r"(smem), "l"(g));
}

#define S_LD   40                   // halves per row: 80B rows, 16B-aligned, conflict-free
#define PLANE  (128 * S_LD)         // halves per (stage, plane)
#define GSMEM  (8 * PLANE * 2)      // bytes: 4 planes x 2 stages = 80KB

// MODE 0 (layer 1): grid (391,2): h-cols [by*128,+128) = relu(m1@W1l^T + x@W1r^T + b1)
// MODE 1 (layer 2): grid (391,2): by==0: g_pf16 = h@W2l^T ; by==1: g_q = h@W2r^T + b2
template <int K, int MODE>
__global__ void __launch_bounds__(256)
gemm_bf16(const float* __restrict__ biasp) {
    extern __shared__ unsigned short sm[];
    unsigned short* Ah = sm;
    unsigned short* Al = Ah + 2 * PLANE;
    unsigned short* Bh = Al + 2 * PLANE;
    unsigned short* Bl = Bh + 2 * PLANE;

    const int t    = threadIdx.x;
    const int wid  = t >> 5;
    const int lane = t & 31;
    const int g    = lane >> 2;
    const int tig  = lane & 3;
    const int wm   = wid & 3;
    const int wn   = wid >> 2;
    const int row0 = blockIdx.x * 128;
    const int by   = blockIdx.y;

    const int a_row = (lane & 7) + ((lane >> 3) & 1) * 8;
    const int a_col = (lane >> 4) * 8;
    const unsigned uAh = (unsigned)__cvta_generic_to_shared(Ah);
    const unsigned uAl = (unsigned)__cvta_generic_to_shared(Al);
    const unsigned uBh = (unsigned)__cvta_generic_to_shared(Bh);
    const unsigned uBl = (unsigned)__cvta_generic_to_shared(Bl);

    float acc[2][8][4];
    #pragma unroll
    for (int im = 0; im < 2; im++)
        #pragma unroll
        for (int in_ = 0; in_ < 8; in_++)
            #pragma unroll
            for (int c = 0; c < 4; c++) acc[im][in_][c] = 0.f;

    const int TC = 8;

    auto copy_chunk = [&](int c, int st) {
        const unsigned short *Aph, *Apl, *Wph, *Wpl;
        int wrow0, kk;
        if (MODE == 0) {
            int pass = c >> 2; kk = (c & 3) * 32;
            Aph = pass ? g_xh : g_m1h;   Apl = pass ? g_xl : g_m1l;
            Wph = pass ? g_w1rh : g_w1lh; Wpl = pass ? g_w1rl : g_w1ll;
            wrow0 = by * 128;
        } else {
            kk = c * 32;
            Aph = g_hh; Apl = g_hl;
            Wph = (by == 0) ? g_w2lh : g_w2rh;
            Wpl = (by == 0) ? g_w2ll : g_w2rl;
            wrow0 = 0;
        }
        #pragma unroll
        for (int u = 0; u < 2; u++) {
            int idx = t + u * 256;
            int row = idx >> 2;
            int c16 = idx & 3;
            int r  = min(row0 + row, NN - 1);
            int wr = wrow0 + row;
            unsigned so = (unsigned)(st * PLANE + row * S_LD) * 2u + (unsigned)c16 * 16u;
            cpa16(uAh + so, Aph + (size_t)r * K + kk + c16 * 8);
            cpa16(uAl + so, Apl + (size_t)r * K + kk + c16 * 8);
            cpa16(uBh + so, Wph + (size_t)wr * K + kk + c16 * 8);
            cpa16(uBl + so, Wpl + (size_t)wr * K + kk + c16 * 8);
        }
        asm volatile("cp.async.commit_group;" ::: "memory");
    };

    auto compute = [&](int st) {
        const unsigned stoff = (unsigned)(st * PLANE) * 2u;
        #pragma unroll
        for (int o = 0; o < 32; o += 16) {
            unsigned ah[2][4], al[2][4], bh[8][2], bl[8][2];
            #pragma unroll
            for (int im = 0; im < 2; im++) {
                unsigned aoff = ((wm * 32 + im * 16 + a_row) * S_LD + o + a_col) * 2u + stoff;
                ldsm_x4(ah[im], uAh + aoff);
                ldsm_x4(al[im], uAl + aoff);
            }
            #pragma unroll
            for (int q = 0; q < 2; q++) {
                #pragma unroll
                for (int kh = 0; kh < 2; kh++) {
                    unsigned boff = ((wn * 64 + q * 32 + lane) * S_LD + o + kh * 8) * 2u + stoff;
                    unsigned r4[4];
                    ldsm_x4(r4, uBh + boff);
                    #pragma unroll
                    for (int j = 0; j < 4; j++) bh[q * 4 + j][kh] = r4[j];
                    ldsm_x4(r4, uBl + boff);
                    #pragma unroll
                    for (int j = 0; j < 4; j++) bl[q * 4 + j][kh] = r4[j];
                }
            }
            #pragma unroll
            for (int im = 0; im < 2; im++)
                #pragma unroll
                for (int in_ = 0; in_ < 8; in_++) {
                    mma_bf16(acc[im][in_], ah[im], bl[in_]);
                    mma_bf16(acc[im][in_], al[im], bh[in_]);
                    mma_bf16(acc[im][in_], ah[im], bh[in_]);
                }
        }
    };

    copy_chunk(0, 0);
    for (int c = 0; c < TC; c++) {
        if (c + 1 < TC) {
            copy_chunk(c + 1, (c + 1) & 1);
            asm volatile("cp.async.wait_group 1;" ::: "memory");
        } else {
            asm volatile("cp.async.wait_group 0;" ::: "memory");
        }
        __syncthreads();
        compute(c & 1);
        __syncthreads();
    }

    // epilogue
    const float* bias = (MODE == 0) ? biasp : ((by == 1) ? biasp : nullptr);
    const int outcol0 = (MODE == 0) ? by * 128 : 0;
    #pragma unroll
    for (int im = 0; im < 2; im++) {
        #pragma unroll
        for (int in_ = 0; in_ < 8; in_++) {
            int col  = wn * 64 + in_ * 8 + 2 * tig;
            int gcol = outcol0 + col;
            float bx = 0.f, byv = 0.f;
            if (bias) { bx = __ldg(bias + gcol); byv = __ldg(bias + gcol + 1); }
            int r0 = row0 + wm * 32 + im * 16 + g;
            #pragma unroll
            for (int half = 0; half < 2; half++) {
                int r = r0 + half * 8;
                if (r >= NN) continue;
                float vx = acc[im][in_][2 * half + 0] + bx;
                float vy = acc[im][in_][2 * half + 1] + byv;
                if (MODE == 0) {
                    vx = fmaxf(vx, 0.f); vy = fmaxf(vy, 0.f);
                    unsigned short hx, lx, hy, ly;
                    split1(vx, hx, lx); split1(vy, hy, ly);
                    *(unsigned*)&g_hh[(size_t)r * HIDC + gcol] = (unsigned)hx | ((unsigned)hy << 16);
                    *(unsigned*)&g_hl[(size_t)r * HIDC + gcol] = (unsigned)lx | ((unsigned)ly << 16);
                } else if (by == 0) {
                    __half2 hv = __floats2half2_rn(vx, vy);
                    *(unsigned*)&g_pf16[(size_t)r * OUTC + col] = *(unsigned*)&hv;
                } else {
                    *(float2*)(g_q + (size_t)r * OUTC + col) = make_float2(vx, vy);
                }
            }
        }
    }
}

// ---------------- launch ----------------
extern "C" void kernel_launch(void* const* d_in, const int* in_sizes, int n_in,
                              void* d_out, int out_size) {
    const float* x   = (const float*)d_in[0];
    const void*  ei  = d_in[1];
    const float* W1l = (const float*)d_in[2];
    const float* b1  = (const float*)d_in[3];
    const float* W1r = (const float*)d_in[4];
    const float* W2l = (const float*)d_in[5];
    const float* b2  = (const float*)d_in[6];
    const float* W2r = (const float*)d_in[7];
    float* out = (float*)d_out;

    cudaFuncSetAttribute(gemm_bf16<INC, 0>,
                         cudaFuncAttributeMaxDynamicSharedMemorySize, GSMEM);
    cudaFuncSetAttribute(gemm_bf16<HIDC, 1>,
                         cudaFuncAttributeMaxDynamicSharedMemorySize, GSMEM);

    const int NB = (NN + 255) / 256;  // 196

    // prep (splits + deg zero + dtype), then one-kernel padded-CSR build
    prep_kernel<<<SWBLK + SXBLK + NB, 256>>>(ei, x, W1l, W1r, W2l, W2r);
    fillpad_kernel<<<(EE + 255) / 256, 256>>>(ei);

    // layer 1: m1 = agg(x_f16);  h = relu(m1@W1l^T + x@W1r^T + b1)
    agg128_kernel<0><<<(NN + 7) / 8, 256>>>(nullptr);
    gemm_bf16<INC, 0><<<dim3((NN + 127) / 128, 2), 256, GSMEM>>>(b1);

    // layer 2: p16 = h@W2l^T; q = h@W2r^T + b2;  out = agg(p16) + q
    gemm_bf16<HIDC, 1><<<dim3((NN + 127) / 128, 2), 256, GSMEM>>>(b2);
    agg128_kernel<1><<<(NN + 7) / 8, 256>>>(out);
}